// round 1
// baseline (speedup 1.0000x reference)
#include <cuda_runtime.h>
#include <cuda_bf16.h>
#include <stdint.h>

// Problem constants
#define Bv 2
#define Nv 4
#define Dv 48
#define Hv 28
#define Wv 60
#define Cv 64
#define NXv 192
#define NYv 192
#define NZv 1
#define NYNX (NYv * NXv)

// Precomputed per-(b,n) combine = R @ inv(K) (row-major 3x3) and translation
__device__ float g_combine[Bv * Nv][9];
__device__ float g_trans[Bv * Nv][3];

// ---------------------------------------------------------------------------
// Setup: invert intrinsics (element-wise division by det to get correctly
// rounded entries, matching LU back-substitution bit-for-bit on this matrix
// structure), multiply by rotation, stash translation.
// ---------------------------------------------------------------------------
__global__ void fp_setup_kernel(const float* __restrict__ intr,
                                const float* __restrict__ pose) {
    int i = threadIdx.x;
    if (i >= Bv * Nv) return;

    const float* K = intr + i * 9;
    float a00 = K[0], a01 = K[1], a02 = K[2];
    float a10 = K[3], a11 = K[4], a12 = K[5];
    float a20 = K[6], a21 = K[7], a22 = K[8];

    float det = __fadd_rn(
        __fsub_rn(__fmul_rn(a00, __fsub_rn(__fmul_rn(a11, a22), __fmul_rn(a12, a21))),
                  __fmul_rn(a01, __fsub_rn(__fmul_rn(a10, a22), __fmul_rn(a12, a20)))),
        __fmul_rn(a02, __fsub_rn(__fmul_rn(a10, a21), __fmul_rn(a11, a20))));

    float inv[9];
    inv[0] = __fdiv_rn(__fsub_rn(__fmul_rn(a11, a22), __fmul_rn(a12, a21)), det);
    inv[1] = __fdiv_rn(__fsub_rn(__fmul_rn(a02, a21), __fmul_rn(a01, a22)), det);
    inv[2] = __fdiv_rn(__fsub_rn(__fmul_rn(a01, a12), __fmul_rn(a02, a11)), det);
    inv[3] = __fdiv_rn(__fsub_rn(__fmul_rn(a12, a20), __fmul_rn(a10, a22)), det);
    inv[4] = __fdiv_rn(__fsub_rn(__fmul_rn(a00, a22), __fmul_rn(a02, a20)), det);
    inv[5] = __fdiv_rn(__fsub_rn(__fmul_rn(a02, a10), __fmul_rn(a00, a12)), det);
    inv[6] = __fdiv_rn(__fsub_rn(__fmul_rn(a10, a21), __fmul_rn(a11, a20)), det);
    inv[7] = __fdiv_rn(__fsub_rn(__fmul_rn(a01, a20), __fmul_rn(a00, a21)), det);
    inv[8] = __fdiv_rn(__fsub_rn(__fmul_rn(a00, a11), __fmul_rn(a01, a10)), det);

    const float* P = pose + i * 16;
    // combine = R @ inv,  R = pose[:3,:3]
    #pragma unroll
    for (int r = 0; r < 3; r++) {
        float r0 = P[r * 4 + 0], r1 = P[r * 4 + 1], r2 = P[r * 4 + 2];
        #pragma unroll
        for (int c = 0; c < 3; c++) {
            float s = __fadd_rn(__fadd_rn(__fmul_rn(r0, inv[0 * 3 + c]),
                                          __fmul_rn(r1, inv[1 * 3 + c])),
                                __fmul_rn(r2, inv[2 * 3 + c]));
            g_combine[i][r * 3 + c] = s;
        }
    }
    g_trans[i][0] = P[3];
    g_trans[i][1] = P[7];
    g_trans[i][2] = P[11];
}

// ---------------------------------------------------------------------------
// Zero the output (harness poisons it to 0xAA)
// ---------------------------------------------------------------------------
__global__ void fp_zero_kernel(float4* __restrict__ out, int n4) {
    int i = blockIdx.x * blockDim.x + threadIdx.x;
    if (i < n4) out[i] = make_float4(0.f, 0.f, 0.f, 0.f);
}

// ---------------------------------------------------------------------------
// Main scatter: one warp per (b, d, h, w). Loops over n, accumulating the
// 64 channels in registers (2 per lane) as long as the target cell is
// unchanged, flushing with atomicAdd (RED) on change. With identical
// cameras this merges all 4 n into one flush -> 4x fewer atomics.
//
// Geometry arithmetic uses explicit round-to-nearest intrinsics (no FMA
// contraction) in the same op order as the JAX reference so the int casts
// are bit-exact.
// ---------------------------------------------------------------------------
__global__ __launch_bounds__(256) void fp_scatter_kernel(
    const float* __restrict__ x, float* __restrict__ out) {
    const int P = Bv * Dv * Hv * Wv;
    int gwarp = (blockIdx.x * blockDim.x + threadIdx.x) >> 5;
    int lane = threadIdx.x & 31;
    if (gwarp >= P) return;

    int w = gwarp % Wv;
    int t = gwarp / Wv;
    int h = t % Hv;
    t /= Hv;
    int d = t % Dv;
    int b = t / Dv;

    // Frustum point (linspace with forced endpoints, matching numpy/jnp)
    float du = __fdiv_rn((float)(Wv * 8 - 1), (float)(Wv - 1));  // 479/59
    float dv = __fdiv_rn((float)(Hv * 8 - 1), (float)(Hv - 1));  // 223/27
    float u = (w == Wv - 1) ? (float)(Wv * 8 - 1) : __fmul_rn((float)w, du);
    float v = (h == Hv - 1) ? (float)(Hv * 8 - 1) : __fmul_rn((float)h, dv);
    float dd = __fadd_rn(2.0f, (float)d);  // DMIN + d*DSTEP
    float ud = __fmul_rn(u, dd);
    float vd = __fmul_rn(v, dd);

    float2 acc = make_float2(0.f, 0.f);
    int cur = -1;

    #pragma unroll
    for (int n = 0; n < Nv; n++) {
        int bn = b * Nv + n;
        const float* cm = g_combine[bn];
        const float* tr = g_trans[bn];

        // geom_i = sum_j cm[i][j] * pts[j]  (j = 0,1,2 sequential), then + trans
        float g0 = __fadd_rn(
            __fadd_rn(__fadd_rn(__fmul_rn(cm[0], ud), __fmul_rn(cm[1], vd)),
                      __fmul_rn(cm[2], dd)),
            tr[0]);
        float g1 = __fadd_rn(
            __fadd_rn(__fadd_rn(__fmul_rn(cm[3], ud), __fmul_rn(cm[4], vd)),
                      __fmul_rn(cm[5], dd)),
            tr[1]);
        float g2 = __fadd_rn(
            __fadd_rn(__fadd_rn(__fmul_rn(cm[6], ud), __fmul_rn(cm[7], vd)),
                      __fmul_rn(cm[8], dd)),
            tr[2]);

        // truncation toward zero matches jnp astype(int32)
        int gx = (int)__fadd_rn(__fmul_rn(g0, 4.0f), 96.0f);
        int gy = (int)__fadd_rn(__fmul_rn(g1, 4.0f), 96.0f);
        int gz = (int)__fdiv_rn(__fadd_rn(g2, 10.0f), 20.0f);

        bool kept = (gx >= 0) & (gx < NXv) & (gy >= 0) & (gy < NYv) &
                    (gz >= 0) & (gz < NZv);

        int cell = kept
            ? ((b * NZv + gz) * Cv * NYNX + gy * NXv + gx)
            : -1;

        if (cell != cur) {
            if (cur >= 0) {
                float* o0 = out + cur + (2 * lane) * NYNX;
                atomicAdd(o0, acc.x);
                atomicAdd(o0 + NYNX, acc.y);
            }
            acc = make_float2(0.f, 0.f);
            cur = cell;
        }
        if (kept) {
            const float2* xv = (const float2*)(x +
                (size_t)((((b * Nv + n) * Dv + d) * Hv + h) * Wv + w) * Cv);
            float2 val = xv[lane];
            acc.x += val.x;
            acc.y += val.y;
        }
    }
    if (cur >= 0) {
        float* o0 = out + cur + (2 * lane) * NYNX;
        atomicAdd(o0, acc.x);
        atomicAdd(o0 + NYNX, acc.y);
    }
}

extern "C" void kernel_launch(void* const* d_in, const int* in_sizes, int n_in,
                              void* d_out, int out_size) {
    const float* x = (const float*)d_in[0];
    const float* intr = (const float*)d_in[1];
    const float* pose = (const float*)d_in[2];
    float* out = (float*)d_out;

    // 1) zero output
    int n4 = out_size / 4;
    fp_zero_kernel<<<(n4 + 255) / 256, 256>>>((float4*)out, n4);

    // 2) per-camera transforms
    fp_setup_kernel<<<1, 32>>>(intr, pose);

    // 3) scatter (one warp per (b,d,h,w), 8 warps per block)
    const int P = Bv * Dv * Hv * Wv;           // 161280 warps
    int blocks = (P + 7) / 8;                  // 256 threads = 8 warps/block
    fp_scatter_kernel<<<blocks, 256>>>(x, out);
}

// round 2
// speedup vs baseline: 1.5161x; 1.5161x over previous
#include <cuda_runtime.h>
#include <cuda_bf16.h>
#include <stdint.h>

// Problem constants
#define Bv 2
#define Nv 4
#define Dv 48
#define Hv 28
#define Wv 60
#define Cv 64
#define NXv 192
#define NYv 192
#define NZv 1
#define NYNX (NYv * NXv)

// Precomputed per-(b,n) combine = R @ inv(K) (row-major 3x3) and translation
__device__ float g_combine[Bv * Nv][9];
__device__ float g_trans[Bv * Nv][3];

// Channel-contiguous staging accumulator: [B*NY*NX][64] floats (18.9 MB)
__device__ float4 g_staging4[(size_t)Bv * NYv * NXv * (Cv / 4)];

// ---------------------------------------------------------------------------
// Setup: invert intrinsics (element-wise division by det — matches LU
// back-substitution bit-for-bit on this matrix), multiply by rotation.
// ---------------------------------------------------------------------------
__global__ void fp_setup_kernel(const float* __restrict__ intr,
                                const float* __restrict__ pose) {
    int i = threadIdx.x;
    if (i >= Bv * Nv) return;

    const float* K = intr + i * 9;
    float a00 = K[0], a01 = K[1], a02 = K[2];
    float a10 = K[3], a11 = K[4], a12 = K[5];
    float a20 = K[6], a21 = K[7], a22 = K[8];

    float det = __fadd_rn(
        __fsub_rn(__fmul_rn(a00, __fsub_rn(__fmul_rn(a11, a22), __fmul_rn(a12, a21))),
                  __fmul_rn(a01, __fsub_rn(__fmul_rn(a10, a22), __fmul_rn(a12, a20)))),
        __fmul_rn(a02, __fsub_rn(__fmul_rn(a10, a21), __fmul_rn(a11, a20))));

    float inv[9];
    inv[0] = __fdiv_rn(__fsub_rn(__fmul_rn(a11, a22), __fmul_rn(a12, a21)), det);
    inv[1] = __fdiv_rn(__fsub_rn(__fmul_rn(a02, a21), __fmul_rn(a01, a22)), det);
    inv[2] = __fdiv_rn(__fsub_rn(__fmul_rn(a01, a12), __fmul_rn(a02, a11)), det);
    inv[3] = __fdiv_rn(__fsub_rn(__fmul_rn(a12, a20), __fmul_rn(a10, a22)), det);
    inv[4] = __fdiv_rn(__fsub_rn(__fmul_rn(a00, a22), __fmul_rn(a02, a20)), det);
    inv[5] = __fdiv_rn(__fsub_rn(__fmul_rn(a02, a10), __fmul_rn(a00, a12)), det);
    inv[6] = __fdiv_rn(__fsub_rn(__fmul_rn(a10, a21), __fmul_rn(a11, a20)), det);
    inv[7] = __fdiv_rn(__fsub_rn(__fmul_rn(a01, a20), __fmul_rn(a00, a21)), det);
    inv[8] = __fdiv_rn(__fsub_rn(__fmul_rn(a00, a11), __fmul_rn(a01, a10)), det);

    const float* P = pose + i * 16;
    #pragma unroll
    for (int r = 0; r < 3; r++) {
        float r0 = P[r * 4 + 0], r1 = P[r * 4 + 1], r2 = P[r * 4 + 2];
        #pragma unroll
        for (int c = 0; c < 3; c++) {
            float s = __fadd_rn(__fadd_rn(__fmul_rn(r0, inv[0 * 3 + c]),
                                          __fmul_rn(r1, inv[1 * 3 + c])),
                                __fmul_rn(r2, inv[2 * 3 + c]));
            g_combine[i][r * 3 + c] = s;
        }
    }
    g_trans[i][0] = P[3];
    g_trans[i][1] = P[7];
    g_trans[i][2] = P[11];
}

// ---------------------------------------------------------------------------
// Zero the staging accumulator
// ---------------------------------------------------------------------------
__global__ void fp_zero_kernel(int n4) {
    int i = blockIdx.x * blockDim.x + threadIdx.x;
    if (i < n4) g_staging4[i] = make_float4(0.f, 0.f, 0.f, 0.f);
}

// ---------------------------------------------------------------------------
// Scatter: one warp = TWO rays (half-warp each). lane&15 selects a group of
// 4 contiguous channels. Accumulate over n in registers while the target
// cell is unchanged (identical cameras -> one flush per ray), flush with a
// single red.global.add.v4.f32 per lane (16 lane-ops/ray instead of 64
// scalar atomics).
//
// Geometry uses explicit round-to-nearest intrinsics in the reference's op
// order so the int32 casts are bit-exact (validated R1: rel_err 2.5e-7).
// ---------------------------------------------------------------------------
__global__ __launch_bounds__(256) void fp_scatter_kernel(
    const float* __restrict__ x) {
    const int P = Bv * Dv * Hv * Wv;  // 161280 rays
    int gwarp = (blockIdx.x * blockDim.x + threadIdx.x) >> 5;
    int lane = threadIdx.x & 31;
    int r = gwarp * 2 + (lane >> 4);
    if (r >= P) return;
    int c4 = (lane & 15) * 4;  // channel group

    int w = r % Wv;
    int t = r / Wv;
    int h = t % Hv;
    t /= Hv;
    int d = t % Dv;
    int b = t / Dv;

    // Frustum point (linspace with forced endpoints, matching numpy/jnp)
    float du = __fdiv_rn((float)(Wv * 8 - 1), (float)(Wv - 1));  // 479/59
    float dv = __fdiv_rn((float)(Hv * 8 - 1), (float)(Hv - 1));  // 223/27
    float u = (w == Wv - 1) ? (float)(Wv * 8 - 1) : __fmul_rn((float)w, du);
    float v = (h == Hv - 1) ? (float)(Hv * 8 - 1) : __fmul_rn((float)h, dv);
    float dd = __fadd_rn(2.0f, (float)d);
    float ud = __fmul_rn(u, dd);
    float vd = __fmul_rn(v, dd);

    float4 acc = make_float4(0.f, 0.f, 0.f, 0.f);
    int cur = -1;

    #pragma unroll
    for (int n = 0; n < Nv; n++) {
        int bn = b * Nv + n;
        const float* cm = g_combine[bn];
        const float* tr = g_trans[bn];

        float g0 = __fadd_rn(
            __fadd_rn(__fadd_rn(__fmul_rn(cm[0], ud), __fmul_rn(cm[1], vd)),
                      __fmul_rn(cm[2], dd)),
            tr[0]);
        float g1 = __fadd_rn(
            __fadd_rn(__fadd_rn(__fmul_rn(cm[3], ud), __fmul_rn(cm[4], vd)),
                      __fmul_rn(cm[5], dd)),
            tr[1]);
        float g2 = __fadd_rn(
            __fadd_rn(__fadd_rn(__fmul_rn(cm[6], ud), __fmul_rn(cm[7], vd)),
                      __fmul_rn(cm[8], dd)),
            tr[2]);

        int gx = (int)__fadd_rn(__fmul_rn(g0, 4.0f), 96.0f);
        int gy = (int)__fadd_rn(__fmul_rn(g1, 4.0f), 96.0f);
        int gz = (int)__fdiv_rn(__fadd_rn(g2, 10.0f), 20.0f);

        bool kept = (gx >= 0) & (gx < NXv) & (gy >= 0) & (gy < NYv) &
                    (gz >= 0) & (gz < NZv);

        int cell = kept ? ((b * NYv + gy) * NXv + gx) : -1;

        if (cell != cur) {
            if (cur >= 0) {
                float* p = (float*)g_staging4 + (size_t)cur * Cv + c4;
                asm volatile(
                    "red.global.add.v4.f32 [%0], {%1, %2, %3, %4};" ::
                    "l"(p), "f"(acc.x), "f"(acc.y), "f"(acc.z), "f"(acc.w)
                    : "memory");
            }
            acc = make_float4(0.f, 0.f, 0.f, 0.f);
            cur = cell;
        }
        if (kept) {
            const float4* xv = (const float4*)(x +
                (size_t)((((b * Nv + n) * Dv + d) * Hv + h) * Wv + w) * Cv + c4);
            float4 val = *xv;
            acc.x += val.x;
            acc.y += val.y;
            acc.z += val.z;
            acc.w += val.w;
        }
    }
    if (cur >= 0) {
        float* p = (float*)g_staging4 + (size_t)cur * Cv + c4;
        asm volatile(
            "red.global.add.v4.f32 [%0], {%1, %2, %3, %4};" ::
            "l"(p), "f"(acc.x), "f"(acc.y), "f"(acc.z), "f"(acc.w)
            : "memory");
    }
}

// ---------------------------------------------------------------------------
// Transpose staging (B, NY, NX, C) -> out (B, C, NY, NX).
// Tile: 32 gx x 64 c in smem (stride 65 -> conflict-free column reads).
// Writes EVERY output element, so it also handles the 0xAA poison.
// ---------------------------------------------------------------------------
__global__ __launch_bounds__(256) void fp_transpose_kernel(float* __restrict__ out) {
    __shared__ float tile[32 * 65];
    int blk = blockIdx.x;
    int gxt = blk % (NXv / 32);
    int t1 = blk / (NXv / 32);
    int gy = t1 % NYv;
    int b = t1 / NYv;
    int gx0 = gxt * 32;
    int t = threadIdx.x;

    const float* src = (const float*)g_staging4 +
        ((size_t)(b * NYv + gy) * NXv + gx0) * Cv;

    #pragma unroll
    for (int it = 0; it < 2; it++) {
        int gx = (t >> 4) + 16 * it;
        int c = (t & 15) * 4;
        float4 vv = *(const float4*)(src + gx * Cv + c);
        tile[gx * 65 + c + 0] = vv.x;
        tile[gx * 65 + c + 1] = vv.y;
        tile[gx * 65 + c + 2] = vv.z;
        tile[gx * 65 + c + 3] = vv.w;
    }
    __syncthreads();

    int lane = t & 31;
    int cw = t >> 5;
    float* dst = out + (size_t)b * Cv * NYNX + gy * NXv + gx0 + lane;
    #pragma unroll
    for (int i = 0; i < 8; i++) {
        int c = cw * 8 + i;
        dst[(size_t)c * NYNX] = tile[lane * 65 + c];
    }
}

extern "C" void kernel_launch(void* const* d_in, const int* in_sizes, int n_in,
                              void* d_out, int out_size) {
    const float* x = (const float*)d_in[0];
    const float* intr = (const float*)d_in[1];
    const float* pose = (const float*)d_in[2];
    float* out = (float*)d_out;

    // 1) zero staging accumulator
    const int n4 = Bv * NYv * NXv * (Cv / 4);  // 1179648
    fp_zero_kernel<<<(n4 + 255) / 256, 256>>>(n4);

    // 2) per-camera transforms
    fp_setup_kernel<<<1, 32>>>(intr, pose);

    // 3) scatter (one warp per 2 rays, vector atomics into staging)
    const int P = Bv * Dv * Hv * Wv;           // 161280 rays
    int warps = P / 2;                          // 80640
    fp_scatter_kernel<<<warps / 8, 256>>>(x);  // 10080 blocks

    // 4) transpose staging -> out (also overwrites poison everywhere)
    int tblocks = Bv * NYv * (NXv / 32);       // 2304
    fp_transpose_kernel<<<tblocks, 256>>>(out);
}